// round 14
// baseline (speedup 1.0000x reference)
#include <cuda_runtime.h>
#include <cuda_fp16.h>
#include <cstdint>

#define NN 200000
#define NPAD 200064     // 1563 * 128
#define DD 128
#define EE 200000
#define EE2 20000
#define SS 6
#define LL 4
#define NBLK 1563
#define S2  136         // uint32 stride for scalar-LDS encoder kernel
#define RSW 68          // fp16 row stride in words (136 halves)
#define RSB 272         // row stride bytes
#define CSTR 132        // fp32 C stride
#define NT 14           // gather edge types
#define CAP3 12         // edges per (type,u) bucket
#define TOTAL_E (12 * EE + 2 * EE2)

#define IMGW (128 * RSW)        // words per prepped B image (8704)
#define IMGB (IMGW * 4)         // 34816 bytes
#define NIMG 16                 // per layer: 14 edge types + ctr + ctr2

// fuse smem layout (bytes): A 34816 | B x2 69632 | Cs 67584
#define X_A 0
#define X_B 34816
#define X_C 104448
#define SMEM_FUSE 172032
#define SMEM_ENC  69632

// ---------------- device scratch ----------------
__device__ float g_feat[NPAD * DD];
__device__ float g_y   [NPAD * DD];
__device__ int   g_cnt3[NT * NPAD];
__device__ int   g_edg3[(size_t)NT * NPAD * CAP3];
__device__ uint32_t g_wimg[4 * NIMG * IMGW];

__device__ __forceinline__ float4 ld4(const float* p) { return *(const float4*)(p); }

__device__ __forceinline__ uint32_t h2(float lo, float hi) {
    uint32_t r;
    asm("cvt.rn.f16x2.f32 %0, %1, %2;" : "=r"(r) : "f"(hi), "f"(lo));
    return r;
}

__device__ __forceinline__ float wsum(float s) {
#pragma unroll
    for (int o = 16; o; o >>= 1) s += __shfl_xor_sync(0xffffffffu, s, o);
    return s;
}

__device__ __forceinline__ uint32_t smem_u32(const void* p) {
    uint32_t a;
    asm("{ .reg .u64 t; cvta.to.shared.u64 t, %1; cvt.u32.u64 %0, t; }" : "=r"(a) : "l"(p));
    return a;
}

__device__ __forceinline__ void cpa16(uint32_t dst, const void* src) {
    asm volatile("cp.async.cg.shared.global [%0], [%1], 16;" :: "r"(dst), "l"(src));
}
__device__ __forceinline__ void cp_commit() {
    asm volatile("cp.async.commit_group;" ::: "memory");
}
template<int N>
__device__ __forceinline__ void cp_wait() {
    asm volatile("cp.async.wait_group %0;" :: "n"(N) : "memory");
}

#define LDSM_X4(r0, r1, r2, r3, addr) \
    asm volatile("ldmatrix.sync.aligned.m8n8.x4.shared.b16 {%0,%1,%2,%3}, [%4];" \
                 : "=r"(r0), "=r"(r1), "=r"(r2), "=r"(r3) : "r"(addr))

#define MMA_F16(acc, a0, a1, a2, a3, b0, b1) \
    asm volatile( \
        "mma.sync.aligned.m16n8k16.row.col.f32.f16.f16.f32 " \
        "{%0,%1,%2,%3}, {%4,%5,%6,%7}, {%8,%9}, {%0,%1,%2,%3};\n" \
        : "+f"((acc)[0]), "+f"((acc)[1]), "+f"((acc)[2]), "+f"((acc)[3]) \
        : "r"(a0), "r"(a1), "r"(a2), "r"(a3), "r"(b0), "r"(b1))

// warp-tile GEMM: acc += A(128x128 fp16 @aB) @ B^T(@bB); 4x4 warp grid, tile 32x32
__device__ __forceinline__ void gemm_acc(uint32_t aB, uint32_t bB, float acc[2][4][4]) {
#pragma unroll
    for (int ks = 0; ks < 8; ks++) {
        uint32_t af0[4], af1[4], bf0[4], bf1[4];
        LDSM_X4(af0[0], af0[1], af0[2], af0[3], aB + ks * 32);
        LDSM_X4(af1[0], af1[1], af1[2], af1[3], aB + 16 * RSB + ks * 32);
        LDSM_X4(bf0[0], bf0[1], bf0[2], bf0[3], bB + ks * 32);
        LDSM_X4(bf1[0], bf1[1], bf1[2], bf1[3], bB + 16 * RSB + ks * 32);
        MMA_F16(acc[0][0], af0[0], af0[1], af0[2], af0[3], bf0[0], bf0[1]);
        MMA_F16(acc[1][0], af1[0], af1[1], af1[2], af1[3], bf0[0], bf0[1]);
        MMA_F16(acc[0][1], af0[0], af0[1], af0[2], af0[3], bf0[2], bf0[3]);
        MMA_F16(acc[1][1], af1[0], af1[1], af1[2], af1[3], bf0[2], bf0[3]);
        MMA_F16(acc[0][2], af0[0], af0[1], af0[2], af0[3], bf1[0], bf1[1]);
        MMA_F16(acc[1][2], af1[0], af1[1], af1[2], af1[3], bf1[0], bf1[1]);
        MMA_F16(acc[0][3], af0[0], af0[1], af0[2], af0[3], bf1[2], bf1[3]);
        MMA_F16(acc[1][3], af1[0], af1[1], af1[2], af1[3], bf1[2], bf1[3]);
    }
}

// ---------------- weight prep ----------------
__global__ __launch_bounds__(256) void prep_kernel(
    const float* __restrict__ pre_w, const float* __restrict__ suc_w,
    const float* __restrict__ left_w, const float* __restrict__ right_w,
    const float* __restrict__ ctr_w, const float* __restrict__ ctr2_w)
{
    int m = blockIdx.x;              // 0..63
    int i = m >> 4, t = m & 15;
    const float* W;
    if (t < 6)        W = pre_w  + (size_t)(i * 6 + t) * 16384;
    else if (t < 12)  W = suc_w  + (size_t)(i * 6 + (t - 6)) * 16384;
    else if (t == 12) W = left_w  + (size_t)i * 16384;
    else if (t == 13) W = right_w + (size_t)i * 16384;
    else if (t == 14) W = ctr_w   + (size_t)i * 16384;
    else              W = ctr2_w  + (size_t)i * 16384;
    uint32_t* img = g_wimg + (size_t)m * IMGW;

    for (int e = threadIdx.x; e < 128 * 64; e += 256) {
        int n = e >> 6, kp = e & 63;
        img[n * RSW + kp] = h2(__ldg(&W[(2 * kp) * 128 + n]), __ldg(&W[(2 * kp + 1) * 128 + n]));
    }
}

// ---------------- per-(type,u) edge buckets ----------------
__global__ void place_kernel(const int* __restrict__ pre_u, const int* __restrict__ pre_v,
                             const int* __restrict__ suc_u, const int* __restrict__ suc_v,
                             const int* __restrict__ left_u, const int* __restrict__ left_v,
                             const int* __restrict__ right_u, const int* __restrict__ right_v)
{
    int idx = blockIdx.x * 256 + threadIdx.x;
    int t, u, v;
    if (idx < 6 * EE)            { t = idx / EE; u = pre_u[idx]; v = pre_v[idx]; }
    else if (idx < 12 * EE)      { int j = idx - 6 * EE; t = idx / EE; u = suc_u[j]; v = suc_v[j]; }
    else if (idx < 12 * EE + EE2){ int j = idx - 12 * EE; t = 12; u = left_u[j]; v = left_v[j]; }
    else if (idx < TOTAL_E)      { int j = idx - 12 * EE - EE2; t = 13; u = right_u[j]; v = right_v[j]; }
    else return;
    int b = t * NPAD + u;
    int pos = atomicAdd(&g_cnt3[b], 1);
    if (pos < CAP3) g_edg3[(size_t)b * CAP3 + pos] = v;
}

// ---------------- encoder stage 1 ----------------
__global__ __launch_bounds__(256) void enc1_kernel(
    const float* __restrict__ ctrs, const float* __restrict__ feats,
    const float* __restrict__ w_in1, const float* __restrict__ b_in1,
    const float* __restrict__ w_seg1, const float* __restrict__ b_seg1,
    float* __restrict__ h_in, float* __restrict__ h_seg)
{
    int idx = blockIdx.x * blockDim.x + threadIdx.x;
    int n = idx >> 5;
    if (n >= NN) return;
    int c = (idx & 31) * 4;

    float c0 = __ldg(&ctrs[2 * n]),  c1 = __ldg(&ctrs[2 * n + 1]);
    float f0 = __ldg(&feats[2 * n]), f1 = __ldg(&feats[2 * n + 1]);

    float4 wi0 = ld4(w_in1 + c), wi1 = ld4(w_in1 + DD + c), bi = ld4(b_in1 + c);
    float4 ws0 = ld4(w_seg1 + c), ws1 = ld4(w_seg1 + DD + c), bs = ld4(b_seg1 + c);

    float4 hi, hs;
    hi.x = fmaxf(c0 * wi0.x + c1 * wi1.x + bi.x, 0.f);
    hi.y = fmaxf(c0 * wi0.y + c1 * wi1.y + bi.y, 0.f);
    hi.z = fmaxf(c0 * wi0.z + c1 * wi1.z + bi.z, 0.f);
    hi.w = fmaxf(c0 * wi0.w + c1 * wi1.w + bi.w, 0.f);
    hs.x = fmaxf(f0 * ws0.x + f1 * ws1.x + bs.x, 0.f);
    hs.y = fmaxf(f0 * ws0.y + f1 * ws1.y + bs.y, 0.f);
    hs.z = fmaxf(f0 * ws0.z + f1 * ws1.z + bs.z, 0.f);
    hs.w = fmaxf(f0 * ws0.w + f1 * ws1.w + bs.w, 0.f);

    *(float4*)&h_in [n * DD + c] = hi;
    *(float4*)&h_seg[n * DD + c] = hs;
}

// ---------------- encoder GEMM (fp16 mma, in-place); grid.y picks the pair ----------------
__global__ __launch_bounds__(256, 2) void enc_gemm2_kernel(
    float* __restrict__ Ain, const float* __restrict__ Ba,
    float* __restrict__ Aseg, const float* __restrict__ Bb)
{
    extern __shared__ char smc[];
    uint32_t* As2 = (uint32_t*)(smc);
    uint32_t* Bs2 = (uint32_t*)(smc + 34816);

    int tid = threadIdx.x, lane = tid & 31, warp = tid >> 5;
    int gid = lane >> 2, tig = lane & 3;
    int wm = warp >> 1, wn = warp & 1;
    long rowBase = (long)blockIdx.x * 128;

    float* A = blockIdx.y ? Aseg : Ain;
    const float* B = blockIdx.y ? Bb : Ba;

    {
        int r = tid >> 1;
        int h = (tid & 1) * 64;
        const float* ap = A + (rowBase + r) * 128 + h;
        int hb = h >> 1;
#pragma unroll
        for (int j = 0; j < 16; j++) {
            float4 a = ld4(ap + j * 4);
            As2[(hb + j * 2 + 0) * S2 + r] = h2(a.x, a.y);
            As2[(hb + j * 2 + 1) * S2 + r] = h2(a.z, a.w);
        }
    }
#pragma unroll
    for (int j = 0; j < 8; j++) {
        int idx = tid + j * 256;
        int kp = idx >> 5, cg = (idx & 31) * 4;
        float4 lo = ld4(B + (2 * kp) * 128 + cg);
        float4 hi = ld4(B + (2 * kp + 1) * 128 + cg);
        uint4 v;
        v.x = h2(lo.x, hi.x);
        v.y = h2(lo.y, hi.y);
        v.z = h2(lo.z, hi.z);
        v.w = h2(lo.w, hi.w);
        *(uint4*)(Bs2 + kp * S2 + cg) = v;
    }
    __syncthreads();

    float acc[2][8][4];
#pragma unroll
    for (int tm = 0; tm < 2; tm++)
#pragma unroll
        for (int nt = 0; nt < 8; nt++)
#pragma unroll
            for (int j = 0; j < 4; j++) acc[tm][nt][j] = 0.f;

#pragma unroll
    for (int ks = 0; ks < 8; ks++) {
        int kk = ks * 8;
        uint32_t af[2][4];
#pragma unroll
        for (int tm = 0; tm < 2; tm++) {
            int rr = wm * 32 + tm * 16 + gid;
            const uint32_t* a0p = As2 + (kk + tig) * S2 + rr;
            const uint32_t* a1p = As2 + (kk + tig + 4) * S2 + rr;
            af[tm][0] = a0p[0];
            af[tm][1] = a0p[8];
            af[tm][2] = a1p[0];
            af[tm][3] = a1p[8];
        }
#pragma unroll
        for (int nt = 0; nt < 8; nt++) {
            int cc = wn * 64 + nt * 8 + gid;
            uint32_t b0 = Bs2[(kk + tig) * S2 + cc];
            uint32_t b1 = Bs2[(kk + tig + 4) * S2 + cc];
#pragma unroll
            for (int tm = 0; tm < 2; tm++)
                MMA_F16(acc[tm][nt], af[tm][0], af[tm][1], af[tm][2], af[tm][3], b0, b1);
        }
    }
    __syncthreads();

#pragma unroll
    for (int tm = 0; tm < 2; tm++) {
        long r0 = rowBase + wm * 32 + tm * 16 + gid;
#pragma unroll
        for (int nt = 0; nt < 8; nt++) {
            int cc = wn * 64 + nt * 8 + tig * 2;
            *(float2*)(A + r0 * 128 + cc)       = make_float2(acc[tm][nt][0], acc[tm][nt][1]);
            *(float2*)(A + (r0 + 8) * 128 + cc) = make_float2(acc[tm][nt][2], acc[tm][nt][3]);
        }
    }
}

// ---------------- GN helper ----------------
__device__ __forceinline__ void gn_stats(float4 x, float& mean, float& kinv) {
    float s  = x.x + x.y + x.z + x.w;
    float sq = x.x * x.x + x.y * x.y + x.z * x.z + x.w * x.w;
    s  = wsum(s)  * (1.f / 128.f);
    sq = wsum(sq) * (1.f / 128.f);
    mean = s;
    float var = sq - s * s;
    kinv = rsqrtf(var + 1e-5f);
}

// enc2: feat = relu(gn(A) + gn(B))
__global__ __launch_bounds__(256) void enc2_kernel(
    const float* __restrict__ A, const float* __restrict__ gA, const float* __restrict__ bA,
    const float* __restrict__ Bv, const float* __restrict__ gB, const float* __restrict__ bB,
    float* __restrict__ feat)
{
    int row = blockIdx.x * 8 + (threadIdx.x >> 5);
    if (row >= NN) return;
    int lane = threadIdx.x & 31;
    int c = lane * 4;
    float4 a = ld4(&A[(long)row * 128 + c]);
    float4 b = ld4(&Bv[(long)row * 128 + c]);
    float ma, ka, mb, kb;
    gn_stats(a, ma, ka);
    gn_stats(b, mb, kb);
    float4 ga = ld4(gA + c), ba = ld4(bA + c);
    float4 gb = ld4(gB + c), bb = ld4(bB + c);
    float4 o;
    o.x = fmaxf((a.x - ma) * ka * ga.x + ba.x + (b.x - mb) * kb * gb.x + bb.x, 0.f);
    o.y = fmaxf((a.y - ma) * ka * ga.y + ba.y + (b.y - mb) * kb * gb.y + bb.y, 0.f);
    o.z = fmaxf((a.z - ma) * ka * ga.z + ba.z + (b.z - mb) * kb * gb.z + bb.z, 0.f);
    o.w = fmaxf((a.w - ma) * ka * ga.w + ba.w + (b.w - mb) * kb * gb.w + bb.w, 0.f);
    *(float4*)&feat[(long)row * 128 + c] = o;
}

// ---------------- fused layer: simple-schedule gather + 15 GEMMs + fused post ----------------
__global__ __launch_bounds__(512) void fuse_kernel(
    const float* __restrict__ featIn, float* __restrict__ featOut,
    const uint32_t* __restrict__ Wimg,
    const float* __restrict__ ng, const float* __restrict__ nb,
    const float* __restrict__ g2, const float* __restrict__ b2,
    float* __restrict__ dout)
{
    extern __shared__ char smc[];
    float* Cs = (float*)(smc + X_C);

    uint32_t sb = smem_u32(smc);
    int tid = threadIdx.x, lane = tid & 31, warp = tid >> 5;
    int gid = lane >> 2, tig = lane & 3;
    int wm = warp >> 2, wn = warp & 3;
    int bid = blockIdx.x;
    long rowBase = (long)bid * 128;
    int wrow = warp * 8;

    uint32_t aLane = (uint32_t)(wm * 32 + (lane & 7) + ((lane & 8) ? 8 : 0)) * RSB
                   + ((lane & 16) ? 16 : 0);
    uint32_t bLane = (uint32_t)(wn * 32 + (lane & 7) + ((lane & 16) ? 8 : 0)) * RSB
                   + ((lane & 8) ? 16 : 0);

    // prologue: B(0) -> slot 0
    for (int ch = tid; ch < IMGB / 16; ch += 512)
        cpa16(sb + X_B + ch * 16, (const char*)Wimg + ch * 16);
    cp_commit();

    float acc[2][4][4];
#pragma unroll
    for (int tm = 0; tm < 2; tm++)
#pragma unroll
        for (int nt = 0; nt < 4; nt++)
#pragma unroll
            for (int j = 0; j < 4; j++) acc[tm][nt][j] = 0.f;

    for (int t = 0; t <= 14; t++) {
        // ---- gather(t) into registers (direct __ldg, 8-row ILP) ----
        float4 facc[8];
        if (t < 14) {
            size_t tb = (size_t)t * NPAD;
            int cnt[8];
            size_t eb[8];
#pragma unroll
            for (int j = 0; j < 8; j++) {
                int u = (int)rowBase + wrow + j;
                int c = __ldg(&g_cnt3[tb + u]);
                cnt[j] = (c > CAP3) ? CAP3 : c;
                eb[j] = (tb + u) * CAP3;
            }
            int v0[8], v1[8];
#pragma unroll
            for (int j = 0; j < 8; j++) v0[j] = (cnt[j] > 0) ? __ldg(&g_edg3[eb[j]]) : 0;
#pragma unroll
            for (int j = 0; j < 8; j++) v1[j] = (cnt[j] > 1) ? __ldg(&g_edg3[eb[j] + 1]) : 0;
#pragma unroll
            for (int j = 0; j < 8; j++) {
                float4 f = ld4(featIn + (size_t)v0[j] * 128 + lane * 4);
                facc[j] = (cnt[j] > 0) ? f : make_float4(0.f, 0.f, 0.f, 0.f);
            }
#pragma unroll
            for (int j = 0; j < 8; j++) {
                if (cnt[j] > 1) {
                    float4 f = ld4(featIn + (size_t)v1[j] * 128 + lane * 4);
                    facc[j].x += f.x; facc[j].y += f.y; facc[j].z += f.z; facc[j].w += f.w;
                }
            }
#pragma unroll
            for (int j = 0; j < 8; j++) {
                for (int e = 2; e < cnt[j]; e++) {
                    int v = __ldg(&g_edg3[eb[j] + e]);
                    float4 f = ld4(featIn + (size_t)v * 128 + lane * 4);
                    facc[j].x += f.x; facc[j].y += f.y; facc[j].z += f.z; facc[j].w += f.w;
                }
            }
        } else {
#pragma unroll
            for (int j = 0; j < 8; j++)
                facc[j] = ld4(featIn + (rowBase + wrow + j) * 128 + lane * 4);
        }

        __syncthreads();   // all warps done reading A(t-1) in prior GEMM

        // store A(t) -> single A buffer (fp16 row-major)
#pragma unroll
        for (int j = 0; j < 8; j++) {
            uint2 v;
            v.x = h2(facc[j].x, facc[j].y);
            v.y = h2(facc[j].z, facc[j].w);
            *(uint2*)(smc + X_A + (wrow + j) * RSB + lane * 8) = v;
        }

        // issue B(t+1) into slot (t+1)&1 (t=14 -> ctr2 image 15), wait B(t)
        {
            const char* src = (const char*)(Wimg + (size_t)(t + 1) * IMGW);
            uint32_t dst = sb + X_B + (uint32_t)((t + 1) & 1) * IMGB;
            for (int ch = tid; ch < IMGB / 16; ch += 512)
                cpa16(dst + ch * 16, src + ch * 16);
            cp_commit();
            cp_wait<1>();
        }
        __syncthreads();   // A(t) + B(t) visible

        gemm_acc(sb + X_A + aLane, sb + X_B + (uint32_t)(t & 1) * IMGB + bLane, acc);
    }

    // ---- fused post ----
    cp_wait<0>();   // ctr2 (slot 1) arrived

    // stage acc (fp32) -> Cs (warp-owned elements)
#pragma unroll
    for (int tm = 0; tm < 2; tm++) {
        int r0 = wm * 32 + tm * 16 + gid;
#pragma unroll
        for (int nt = 0; nt < 4; nt++) {
            int cc = wn * 32 + nt * 8 + tig * 2;
            *(float2*)(Cs + r0 * CSTR + cc)       = make_float2(acc[tm][nt][0], acc[tm][nt][1]);
            *(float2*)(Cs + (r0 + 8) * CSTR + cc) = make_float2(acc[tm][nt][2], acc[tm][nt][3]);
        }
    }
    __syncthreads();   // stages visible; all GEMM(14) A reads done

    // GN1 + relu -> fp16 tile at X_A
#pragma unroll
    for (int j = 0; j < 8; j++) {
        int r = wrow + j;
        int c = lane * 4;
        float4 x = *(float4*)(Cs + r * CSTR + c);
        float m, k;
        gn_stats(x, m, k);
        float4 gg = ld4(ng + c), bb = ld4(nb + c);
        uint2 v;
        v.x = h2(fmaxf((x.x - m) * k * gg.x + bb.x, 0.f),
                 fmaxf((x.y - m) * k * gg.y + bb.y, 0.f));
        v.y = h2(fmaxf((x.z - m) * k * gg.z + bb.z, 0.f),
                 fmaxf((x.w - m) * k * gg.w + bb.w, 0.f));
        *(uint2*)(smc + X_A + r * RSB + lane * 8) = v;
    }
    __syncthreads();

    // GEMM2: acc2 = GN1 @ ctr2 (slot 1)
    float acc2[2][4][4];
#pragma unroll
    for (int tm = 0; tm < 2; tm++)
#pragma unroll
        for (int nt = 0; nt < 4; nt++)
#pragma unroll
            for (int j = 0; j < 4; j++) acc2[tm][nt][j] = 0.f;
    gemm_acc(sb + X_A + aLane, sb + X_B + IMGB + bLane, acc2);

    // stage acc2 -> Cs
#pragma unroll
    for (int tm = 0; tm < 2; tm++) {
        int r0 = wm * 32 + tm * 16 + gid;
#pragma unroll
        for (int nt = 0; nt < 4; nt++) {
            int cc = wn * 32 + nt * 8 + tig * 2;
            *(float2*)(Cs + r0 * CSTR + cc)       = make_float2(acc2[tm][nt][0], acc2[tm][nt][1]);
            *(float2*)(Cs + (r0 + 8) * CSTR + cc) = make_float2(acc2[tm][nt][2], acc2[tm][nt][3]);
        }
    }
    __syncthreads();

    // GN2 + residual + relu -> featOut (+dout)
#pragma unroll
    for (int j = 0; j < 8; j++) {
        int r = wrow + j;
        int c = lane * 4;
        float4 x = *(float4*)(Cs + r * CSTR + c);
        float m, k;
        gn_stats(x, m, k);
        float4 gg = ld4(g2 + c), bb = ld4(b2 + c);
        long grow = rowBase + r;
        float4 old = ld4(featIn + grow * 128 + c);
        float4 o;
        o.x = fmaxf((x.x - m) * k * gg.x + bb.x + old.x, 0.f);
        o.y = fmaxf((x.y - m) * k * gg.y + bb.y + old.y, 0.f);
        o.z = fmaxf((x.z - m) * k * gg.z + bb.z + old.z, 0.f);
        o.w = fmaxf((x.w - m) * k * gg.w + bb.w + old.w, 0.f);
        *(float4*)(featOut + grow * 128 + c) = o;
        if (dout && grow < NN) *(float4*)(dout + grow * 128 + c) = o;
    }
}

// ---------------- host launcher ----------------
extern "C" void kernel_launch(void* const* d_in, const int* in_sizes, int n_in,
                              void* d_out, int out_size)
{
    const float* ctrs   = (const float*)d_in[0];
    const float* feats  = (const float*)d_in[1];
    const float* w_in1  = (const float*)d_in[2];
    const float* b_in1  = (const float*)d_in[3];
    const float* w_in2  = (const float*)d_in[4];
    const float* g_in   = (const float*)d_in[5];
    const float* be_in  = (const float*)d_in[6];
    const float* w_seg1 = (const float*)d_in[7];
    const float* b_seg1 = (const float*)d_in[8];
    const float* w_seg2 = (const float*)d_in[9];
    const float* g_seg  = (const float*)d_in[10];
    const float* be_seg = (const float*)d_in[11];
    const float* ctr_w  = (const float*)d_in[12];
    const float* pre_w  = (const float*)d_in[13];
    const float* suc_w  = (const float*)d_in[14];
    const float* left_w = (const float*)d_in[15];
    const float* right_w= (const float*)d_in[16];
    const float* norm_g = (const float*)d_in[17];
    const float* norm_b = (const float*)d_in[18];
    const float* ctr2_w = (const float*)d_in[19];
    const float* ctr2_g = (const float*)d_in[20];
    const float* ctr2_b = (const float*)d_in[21];
    const int* pre_u  = (const int*)d_in[22];
    const int* pre_v  = (const int*)d_in[23];
    const int* suc_u  = (const int*)d_in[24];
    const int* suc_v  = (const int*)d_in[25];
    const int* left_u = (const int*)d_in[26];
    const int* left_v = (const int*)d_in[27];
    const int* right_u= (const int*)d_in[28];
    const int* right_v= (const int*)d_in[29];

    float *featA, *featB;
    int *cnt3;
    uint32_t *wimg;
    cudaGetSymbolAddress((void**)&featA, g_feat);
    cudaGetSymbolAddress((void**)&featB, g_y);
    cudaGetSymbolAddress((void**)&cnt3,  g_cnt3);
    cudaGetSymbolAddress((void**)&wimg,  g_wimg);

    const int EB = (TOTAL_E + 255) / 256;

    static bool attr_set = false;
    if (!attr_set) {
        cudaFuncSetAttribute(enc_gemm2_kernel, cudaFuncAttributeMaxDynamicSharedMemorySize, SMEM_ENC);
        cudaFuncSetAttribute(fuse_kernel,      cudaFuncAttributeMaxDynamicSharedMemorySize, SMEM_FUSE);
        attr_set = true;
    }

    cudaMemsetAsync(cnt3, 0, (size_t)NT * NPAD * sizeof(int));
    place_kernel<<<EB, 256>>>(pre_u, pre_v, suc_u, suc_v, left_u, left_v, right_u, right_v);
    prep_kernel<<<64, 256>>>(pre_w, suc_w, left_w, right_w, ctr_w, ctr2_w);

    enc1_kernel<<<(NN * 32) / 256, 256>>>(ctrs, feats, w_in1, b_in1, w_seg1, b_seg1, featA, featB);
    enc_gemm2_kernel<<<dim3(NBLK, 2), 256, SMEM_ENC>>>(featA, w_in2, featB, w_seg2);
    enc2_kernel<<<NN / 8, 256>>>(featA, g_in, be_in, featB, g_seg, be_seg, featA);

    for (int i = 0; i < LL; i++) {
        const float* fin  = (i & 1) ? featB : featA;
        float*       fout = (i & 1) ? featA : featB;
        fuse_kernel<<<NBLK, 512, SMEM_FUSE>>>(
            fin, fout, wimg + (size_t)i * NIMG * IMGW,
            norm_g + i * 128, norm_b + i * 128,
            ctr2_g + i * 128, ctr2_b + i * 128,
            (i == LL - 1) ? (float*)d_out : nullptr);
    }
}

// round 16
// speedup vs baseline: 1.5600x; 1.5600x over previous
#include <cuda_runtime.h>
#include <cuda_fp16.h>
#include <cstdint>

#define NN 200000
#define NPAD 200064     // 1563 * 128
#define DD 128
#define EE 200000
#define EE2 20000
#define SS 6
#define LL 4
#define NBLK 1563
#define S2  136         // uint32 stride for scalar-LDS encoder kernel
#define RSW 68          // fp16 row stride in words (136 halves)
#define RSB 272         // row stride bytes
#define CSTR 132        // fp32 C stride (post kernel)
#define NTYPE 14
#define NBUCK (NTYPE * NBLK)
#define TOTAL_E (12 * EE + 2 * EE2)
#define CAP1 256
#define CAP2 64
#define EDGESZ (12 * NBLK * CAP1 + 2 * NBLK * CAP2)

#define IMGW (128 * RSW)        // uint32 words per prepped B image (8704)
#define IMGB (IMGW * 4)         // 34816 bytes
#define CHW  (128 * RSW)        // fp16 C buffer words
#define NIMG 16                 // per layer: 14 edge types + ctr + ctr2

// fuse smem layout (bytes)
#define F_A   0                          // A tile (ldmatrix layout): 34816
#define F_B   34816                      // B x2: 69632
#define F_C   (34816 + 69632)            // CH x2 (fp16): 69632
#define F_E   (34816 + 69632 + 69632)    // EIX: 12800
#define F_CNT (F_E + 12800)              // SCNT: 64
#define SMEM_FUSE4 (F_CNT + 64)          // 186944
#define SMEM_POST 69632
#define SMEM_ENC  69632

// ---------------- device scratch ----------------
__device__ float g_feat[NPAD * DD];
__device__ float g_y   [NPAD * DD];
__device__ float g_tmp [NPAD * DD];
__device__ int   g_cnt [NBUCK];
__device__ int   g_edges[EDGESZ];
__device__ uint32_t g_wimg[4 * NIMG * IMGW];

__device__ __forceinline__ float4 ld4(const float* p) { return *(const float4*)(p); }

__device__ __forceinline__ uint32_t h2(float lo, float hi) {
    uint32_t r;
    asm("cvt.rn.f16x2.f32 %0, %1, %2;" : "=r"(r) : "f"(hi), "f"(lo));
    return r;
}

__device__ __forceinline__ float wsum(float s) {
#pragma unroll
    for (int o = 16; o; o >>= 1) s += __shfl_xor_sync(0xffffffffu, s, o);
    return s;
}

__device__ __forceinline__ void redv4(float* p, float4 y) {
    asm volatile("red.global.add.v4.f32 [%0], {%1,%2,%3,%4};"
                 :: "l"(p), "f"(y.x), "f"(y.y), "f"(y.z), "f"(y.w) : "memory");
}

__device__ __forceinline__ uint32_t smem_u32(const void* p) {
    uint32_t a;
    asm("{ .reg .u64 t; cvta.to.shared.u64 t, %1; cvt.u32.u64 %0, t; }" : "=r"(a) : "l"(p));
    return a;
}

__device__ __forceinline__ void cpa16(uint32_t dst, const void* src) {
    asm volatile("cp.async.cg.shared.global [%0], [%1], 16;" :: "r"(dst), "l"(src));
}
__device__ __forceinline__ void cp_commit() {
    asm volatile("cp.async.commit_group;" ::: "memory");
}
template<int N>
__device__ __forceinline__ void cp_wait() {
    asm volatile("cp.async.wait_group %0;" :: "n"(N) : "memory");
}

#define LDSM_X4(r0, r1, r2, r3, addr) \
    asm volatile("ldmatrix.sync.aligned.m8n8.x4.shared.b16 {%0,%1,%2,%3}, [%4];" \
                 : "=r"(r0), "=r"(r1), "=r"(r2), "=r"(r3) : "r"(addr))

#define MMA_F16(acc, a0, a1, a2, a3, b0, b1) \
    asm volatile( \
        "mma.sync.aligned.m16n8k16.row.col.f32.f16.f16.f32 " \
        "{%0,%1,%2,%3}, {%4,%5,%6,%7}, {%8,%9}, {%0,%1,%2,%3};\n" \
        : "+f"((acc)[0]), "+f"((acc)[1]), "+f"((acc)[2]), "+f"((acc)[3]) \
        : "r"(a0), "r"(a1), "r"(a2), "r"(a3), "r"(b0), "r"(b1))

// ---------------- weight prep: fp32 W[k][n] -> fp16 image W^T [n][k], stride RSW ----------------
__global__ __launch_bounds__(256) void prep_kernel(
    const float* __restrict__ pre_w, const float* __restrict__ suc_w,
    const float* __restrict__ left_w, const float* __restrict__ right_w,
    const float* __restrict__ ctr_w, const float* __restrict__ ctr2_w)
{
    int m = blockIdx.x;              // 0..63
    int i = m >> 4, t = m & 15;
    const float* W;
    if (t < 6)        W = pre_w  + (size_t)(i * 6 + t) * 16384;
    else if (t < 12)  W = suc_w  + (size_t)(i * 6 + (t - 6)) * 16384;
    else if (t == 12) W = left_w  + (size_t)i * 16384;
    else if (t == 13) W = right_w + (size_t)i * 16384;
    else if (t == 14) W = ctr_w   + (size_t)i * 16384;
    else              W = ctr2_w  + (size_t)i * 16384;
    uint32_t* img = g_wimg + (size_t)m * IMGW;

    for (int e = threadIdx.x; e < 128 * 64; e += 256) {
        int n = e >> 6, kp = e & 63;
        img[n * RSW + kp] = h2(__ldg(&W[(2 * kp) * 128 + n]), __ldg(&W[(2 * kp + 1) * 128 + n]));
    }
}

// ---------------- edge buckets (type, v-block); relies on g_cnt zeroed ----------------
__global__ void place_kernel(const int* __restrict__ pre_u, const int* __restrict__ pre_v,
                             const int* __restrict__ suc_u, const int* __restrict__ suc_v,
                             const int* __restrict__ left_u, const int* __restrict__ left_v,
                             const int* __restrict__ right_u, const int* __restrict__ right_v)
{
    int idx = blockIdx.x * 256 + threadIdx.x;
    int t, u, v;
    if (idx < 6 * EE)            { t = idx / EE; u = pre_u[idx]; v = pre_v[idx]; }
    else if (idx < 12 * EE)      { int j = idx - 6 * EE; t = idx / EE; u = suc_u[j]; v = suc_v[j]; }
    else if (idx < 12 * EE + EE2){ int j = idx - 12 * EE; t = 12; u = left_u[j]; v = left_v[j]; }
    else if (idx < TOTAL_E)      { int j = idx - 12 * EE - EE2; t = 13; u = right_u[j]; v = right_v[j]; }
    else return;
    int vb = v >> 7;
    int b = t * NBLK + vb;
    int cap  = (t < 12) ? CAP1 : CAP2;
    int base = (t < 12) ? b * CAP1 : (12 * NBLK * CAP1 + ((t - 12) * NBLK + vb) * CAP2);
    int pos = atomicAdd(&g_cnt[b], 1);
    if (pos < cap) g_edges[base + pos] = u | ((v & 127) << 18);
}

// ---------------- encoder stage 1 ----------------
__global__ __launch_bounds__(256) void enc1_kernel(
    const float* __restrict__ ctrs, const float* __restrict__ feats,
    const float* __restrict__ w_in1, const float* __restrict__ b_in1,
    const float* __restrict__ w_seg1, const float* __restrict__ b_seg1,
    float* __restrict__ h_in, float* __restrict__ h_seg)
{
    int idx = blockIdx.x * blockDim.x + threadIdx.x;
    int n = idx >> 5;
    if (n >= NN) return;
    int c = (idx & 31) * 4;

    float c0 = __ldg(&ctrs[2 * n]),  c1 = __ldg(&ctrs[2 * n + 1]);
    float f0 = __ldg(&feats[2 * n]), f1 = __ldg(&feats[2 * n + 1]);

    float4 wi0 = ld4(w_in1 + c), wi1 = ld4(w_in1 + DD + c), bi = ld4(b_in1 + c);
    float4 ws0 = ld4(w_seg1 + c), ws1 = ld4(w_seg1 + DD + c), bs = ld4(b_seg1 + c);

    float4 hi, hs;
    hi.x = fmaxf(c0 * wi0.x + c1 * wi1.x + bi.x, 0.f);
    hi.y = fmaxf(c0 * wi0.y + c1 * wi1.y + bi.y, 0.f);
    hi.z = fmaxf(c0 * wi0.z + c1 * wi1.z + bi.z, 0.f);
    hi.w = fmaxf(c0 * wi0.w + c1 * wi1.w + bi.w, 0.f);
    hs.x = fmaxf(f0 * ws0.x + f1 * ws1.x + bs.x, 0.f);
    hs.y = fmaxf(f0 * ws0.y + f1 * ws1.y + bs.y, 0.f);
    hs.z = fmaxf(f0 * ws0.z + f1 * ws1.z + bs.z, 0.f);
    hs.w = fmaxf(f0 * ws0.w + f1 * ws1.w + bs.w, 0.f);

    *(float4*)&h_in [n * DD + c] = hi;
    *(float4*)&h_seg[n * DD + c] = hs;
}

// ---------------- encoder GEMM (fp16 mma, in-place); grid.y picks the pair ----------------
__global__ __launch_bounds__(256, 2) void enc_gemm2_kernel(
    float* __restrict__ Ain, const float* __restrict__ Ba,
    float* __restrict__ Aseg, const float* __restrict__ Bb)
{
    extern __shared__ char smc[];
    uint32_t* As2 = (uint32_t*)(smc);
    uint32_t* Bs2 = (uint32_t*)(smc + 34816);

    int tid = threadIdx.x, lane = tid & 31, warp = tid >> 5;
    int gid = lane >> 2, tig = lane & 3;
    int wm = warp >> 1, wn = warp & 1;
    long rowBase = (long)blockIdx.x * 128;

    float* A = blockIdx.y ? Aseg : Ain;
    const float* B = blockIdx.y ? Bb : Ba;

    {
        int r = tid >> 1;
        int h = (tid & 1) * 64;
        const float* ap = A + (rowBase + r) * 128 + h;
        int hb = h >> 1;
#pragma unroll
        for (int j = 0; j < 16; j++) {
            float4 a = ld4(ap + j * 4);
            As2[(hb + j * 2 + 0) * S2 + r] = h2(a.x, a.y);
            As2[(hb + j * 2 + 1) * S2 + r] = h2(a.z, a.w);
        }
    }
#pragma unroll
    for (int j = 0; j < 8; j++) {
        int idx = tid + j * 256;
        int kp = idx >> 5, cg = (idx & 31) * 4;
        float4 lo = ld4(B + (2 * kp) * 128 + cg);
        float4 hi = ld4(B + (2 * kp + 1) * 128 + cg);
        uint4 v;
        v.x = h2(lo.x, hi.x);
        v.y = h2(lo.y, hi.y);
        v.z = h2(lo.z, hi.z);
        v.w = h2(lo.w, hi.w);
        *(uint4*)(Bs2 + kp * S2 + cg) = v;
    }
    __syncthreads();

    float acc[2][8][4];
#pragma unroll
    for (int tm = 0; tm < 2; tm++)
#pragma unroll
        for (int nt = 0; nt < 8; nt++)
#pragma unroll
            for (int j = 0; j < 4; j++) acc[tm][nt][j] = 0.f;

#pragma unroll
    for (int ks = 0; ks < 8; ks++) {
        int kk = ks * 8;
        uint32_t af[2][4];
#pragma unroll
        for (int tm = 0; tm < 2; tm++) {
            int rr = wm * 32 + tm * 16 + gid;
            const uint32_t* a0p = As2 + (kk + tig) * S2 + rr;
            const uint32_t* a1p = As2 + (kk + tig + 4) * S2 + rr;
            af[tm][0] = a0p[0];
            af[tm][1] = a0p[8];
            af[tm][2] = a1p[0];
            af[tm][3] = a1p[8];
        }
#pragma unroll
        for (int nt = 0; nt < 8; nt++) {
            int cc = wn * 64 + nt * 8 + gid;
            uint32_t b0 = Bs2[(kk + tig) * S2 + cc];
            uint32_t b1 = Bs2[(kk + tig + 4) * S2 + cc];
#pragma unroll
            for (int tm = 0; tm < 2; tm++)
                MMA_F16(acc[tm][nt], af[tm][0], af[tm][1], af[tm][2], af[tm][3], b0, b1);
        }
    }
    __syncthreads();

#pragma unroll
    for (int tm = 0; tm < 2; tm++) {
        long r0 = rowBase + wm * 32 + tm * 16 + gid;
#pragma unroll
        for (int nt = 0; nt < 8; nt++) {
            int cc = wn * 64 + nt * 8 + tig * 2;
            *(float2*)(A + r0 * 128 + cc)       = make_float2(acc[tm][nt][0], acc[tm][nt][1]);
            *(float2*)(A + (r0 + 8) * 128 + cc) = make_float2(acc[tm][nt][2], acc[tm][nt][3]);
        }
    }
}

// ---------------- GN helpers ----------------
__device__ __forceinline__ void gn_stats(float4 x, float& mean, float& kinv) {
    float s  = x.x + x.y + x.z + x.w;
    float sq = x.x * x.x + x.y * x.y + x.z * x.z + x.w * x.w;
    s  = wsum(s)  * (1.f / 128.f);
    sq = wsum(sq) * (1.f / 128.f);
    mean = s;
    float var = sq - s * s;
    kinv = rsqrtf(var + 1e-5f);
}

// enc2: feat = relu(gn(A) + gn(B)); zero A rows (tmp) for iter 0
__global__ __launch_bounds__(256) void enc2_kernel(
    float* __restrict__ A, const float* __restrict__ gA, const float* __restrict__ bA,
    const float* __restrict__ Bv, const float* __restrict__ gB, const float* __restrict__ bB,
    float* __restrict__ feat)
{
    int row = blockIdx.x * 8 + (threadIdx.x >> 5);
    if (row >= NN) return;
    int lane = threadIdx.x & 31;
    int c = lane * 4;
    float4 a = ld4(&A[(long)row * 128 + c]);
    float4 b = ld4(&Bv[(long)row * 128 + c]);
    float ma, ka, mb, kb;
    gn_stats(a, ma, ka);
    gn_stats(b, mb, kb);
    float4 ga = ld4(gA + c), ba = ld4(bA + c);
    float4 gb = ld4(gB + c), bb = ld4(bB + c);
    float4 o;
    o.x = fmaxf((a.x - ma) * ka * ga.x + ba.x + (b.x - mb) * kb * gb.x + bb.x, 0.f);
    o.y = fmaxf((a.y - ma) * ka * ga.y + ba.y + (b.y - mb) * kb * gb.y + bb.y, 0.f);
    o.z = fmaxf((a.z - ma) * ka * ga.z + ba.z + (b.z - mb) * kb * gb.z + bb.z, 0.f);
    o.w = fmaxf((a.w - ma) * ka * ga.w + ba.w + (b.w - mb) * kb * gb.w + bb.w, 0.f);
    *(float4*)&feat[(long)row * 128 + c] = o;
    *(float4*)&A   [(long)row * 128 + c] = make_float4(0.f, 0.f, 0.f, 0.f);
}

// ---------------- fuse: warp-specialized (w0-7 GEMM, w8-15 scatter) ----------------
__global__ __launch_bounds__(512) void fuse_kernel(
    const float* __restrict__ featIn, float* __restrict__ temp,
    const uint32_t* __restrict__ Wimg)
{
    extern __shared__ char smc[];
    uint32_t* CH  = (uint32_t*)(smc + F_C);
    int*      EIX = (int*)(smc + F_E);
    int*      SCNT= (int*)(smc + F_CNT);

    uint32_t sb = smem_u32(smc);
    uint32_t eixA = sb + F_E;

    int tid = threadIdx.x, lane = tid & 31, warp = tid >> 5;
    int gid = lane >> 2, tig = lane & 3;
    int bid = blockIdx.x;
    long rowBase = (long)bid * 128;

    // compute-warp geometry (warps 0-7): 4x2 grid, warp tile 32x64
    int wm = (warp & 7) >> 1, wn = warp & 1;

    // --- async group 0: edge indices + B(0) ---
    for (int ch = tid; ch < 800; ch += 512) {
        int w = ch * 4;
        int srcw;
        if (w < 3072) {
            int t = w >> 8, off = w & 255;
            srcw = (t * NBLK + bid) * CAP1 + off;
        } else {
            int j = w - 3072;
            int t = j >> 6, off = j & 63;
            srcw = 12 * NBLK * CAP1 + (t * NBLK + bid) * CAP2 + off;
        }
        cpa16(eixA + w * 4, g_edges + srcw);
    }
    for (int ch = tid; ch < IMGB / 16; ch += 512)
        cpa16(sb + F_B + ch * 16, (const char*)Wimg + ch * 16);
    cp_commit();

    // --- bucket counts -> smem ---
    if (tid < 14) {
        int c = g_cnt[tid * NBLK + bid];
        int cap = (tid < 12) ? CAP1 : CAP2;
        SCNT[tid] = (c > cap) ? cap : c;
    }

    // --- A tile: row-major fp16 [row][k], stride RSW words ---
    {
        int r = tid >> 2, q = tid & 3;
        const float* ap = featIn + (rowBase + r) * 128 + q * 32;
        char* dst = smc + F_A + r * RSB + q * 64;
#pragma unroll
        for (int j = 0; j < 8; j++) {
            float4 a = ld4(ap + j * 4);
            uint2 v;
            v.x = h2(a.x, a.y);
            v.y = h2(a.z, a.w);
            *(uint2*)(dst + j * 8) = v;
        }
    }

    // ldmatrix base addresses (compute warps)
    uint32_t aBase = sb + F_A
        + (uint32_t)(wm * 32 + (lane & 7) + ((lane & 8) ? 8 : 0)) * RSB
        + ((lane & 16) ? 16 : 0);
    uint32_t bBase = sb + F_B
        + (uint32_t)(wn * 64 + (lane & 7) + ((lane & 16) ? 8 : 0)) * RSB
        + ((lane & 8) ? 16 : 0);

    for (int t = 0; t < 15; t++) {
        cp_wait<0>();
        __syncthreads();   // B(t)+edges visible; C(t-1) staged; scatter(t-2) done with CH[t&1]

        // issue B(t+1) into other buffer (all threads; cheap)
        if (t < 14) {
            const char* src = (const char*)(Wimg + (size_t)(t + 1) * IMGW);
            uint32_t dst = sb + F_B + ((t + 1) & 1) * IMGB;
            for (int ch = tid; ch < IMGB / 16; ch += 512)
                cpa16(dst + ch * 16, src + ch * 16);
            cp_commit();
        }

        if (warp < 8) {
            // ---- compute warps: GEMM(t) + stage C(t) ----
            float acc[2][8][4];
#pragma unroll
            for (int tm = 0; tm < 2; tm++)
#pragma unroll
                for (int nt = 0; nt < 8; nt++)
#pragma unroll
                    for (int j = 0; j < 4; j++) acc[tm][nt][j] = 0.f;

#pragma unroll
            for (int ks = 0; ks < 8; ks++) {
                uint32_t af0[4], af1[4];
                LDSM_X4(af0[0], af0[1], af0[2], af0[3], aBase + ks * 32);
                LDSM_X4(af1[0], af1[1], af1[2], af1[3], aBase + 16 * RSB + ks * 32);
#pragma unroll
                for (int g = 0; g < 4; g++) {
                    uint32_t bf[4];
                    LDSM_X4(bf[0], bf[1], bf[2], bf[3], bBase + (uint32_t)(t & 1) * IMGB
                            + (uint32_t)g * 16 * RSB + ks * 32);
                    MMA_F16(acc[0][2 * g],     af0[0], af0[1], af0[2], af0[3], bf[0], bf[1]);
                    MMA_F16(acc[1][2 * g],     af1[0], af1[1], af1[2], af1[3], bf[0], bf[1]);
                    MMA_F16(acc[0][2 * g + 1], af0[0], af0[1], af0[2], af0[3], bf[2], bf[3]);
                    MMA_F16(acc[1][2 * g + 1], af1[0], af1[1], af1[2], af1[3], bf[2], bf[3]);
                }
            }

            // stage C(t) fp16 -> CH[t&1]
            uint32_t* Cw = CH + ((t & 1) ? CHW : 0);
#pragma unroll
            for (int tm = 0; tm < 2; tm++) {
                int r0 = wm * 32 + tm * 16 + gid;
#pragma unroll
                for (int nt = 0; nt < 8; nt++) {
                    int widx = wn * 32 + nt * 4 + tig;
                    Cw[r0 * RSW + widx]       = h2(acc[tm][nt][0], acc[tm][nt][1]);
                    Cw[(r0 + 8) * RSW + widx] = h2(acc[tm][nt][2], acc[tm][nt][3]);
                }
            }
        } else if (t > 0) {
            // ---- scatter warps: drain CH[(t-1)&1] ----
            int s = t - 1;
            int sw = warp - 8;
            int len = SCNT[s];
            int ebase = (s < 12) ? s * CAP1 : 3072 + (s - 12) * CAP2;
            const uint32_t* Crow = CH + ((s & 1) ? CHW : 0);
            for (int e = sw; e < len; e += 8) {
                int pk = EIX[ebase + e];
                int u  = pk & 0x3FFFF;
                int vl = pk >> 18;
                uint2 w = *(const uint2*)(Crow + vl * RSW + lane * 2);
                float2 f0 = __half22float2(*(__half2*)&w.x);
                float2 f1 = __half22float2(*(__half2*)&w.y);
                redv4(temp + (long)u * 128 + lane * 4, make_float4(f0.x, f0.y, f1.x, f1.y));
            }
        }
    }

    // drain: ctr rows only (staged in CH[0] at t=14; s=0..13 all scattered in-loop)
    __syncthreads();
    for (int r = warp; r < 128; r += 16) {
        uint2 w = *(const uint2*)(CH + r * RSW + lane * 2);
        float2 f0 = __half22float2(*(__half2*)&w.x);
        float2 f1 = __half22float2(*(__half2*)&w.y);
        redv4(temp + (rowBase + r) * 128 + lane * 4, make_float4(f0.x, f0.y, f1.x, f1.y));
    }
}

// ---------------- post (ldmatrix + cp.async B image) ----------------
__global__ __launch_bounds__(256, 2) void post_kernel(
    float* __restrict__ tmp, float* __restrict__ feat,
    const uint32_t* __restrict__ Bimg,
    const float* __restrict__ ng, const float* __restrict__ nb,
    const float* __restrict__ g2, const float* __restrict__ b2,
    float* __restrict__ dout, int zero_tmp, int zero_cnt)
{
    extern __shared__ char smc[];
    float* Cs = (float*)(smc);

    uint32_t sb = smem_u32(smc);
    int tid = threadIdx.x, lane = tid & 31, warp = tid >> 5;
    int gid = lane >> 2, tig = lane & 3;
    int wm = warp >> 1, wn = warp & 1;
    long rowBase = (long)blockIdx.x * 128;

    for (int ch = tid; ch < IMGB / 16; ch += 256)
        cpa16(sb + 34816 + ch * 16, (const char*)Bimg + ch * 16);
    cp_commit();

    if (zero_cnt && tid < 14) g_cnt[blockIdx.x * 14 + tid] = 0;

    {
        int r = tid >> 1;
        int h = (tid & 1) * 64;
        float* xp = tmp + (rowBase + r) * 128 + h;
        float s = 0.f, sq = 0.f;
        float4 av[16];
#pragma unroll
        for (int j = 0; j < 16; j++) {
            av[j] = ld4(xp + j * 4);
            s  += av[j].x + av[j].y + av[j].z + av[j].w;
            sq += av[j].x * av[j].x + av[j].y * av[j].y + av[j].z * av[j].z + av[j].w * av[j].w;
        }
        s  += __shfl_xor_sync(0xffffffffu, s, 1);
        sq += __shfl_xor_sync(0xffffffffu, sq, 1);
        float mean = s * (1.f / 128.f);
        float kinv = rsqrtf(sq * (1.f / 128.f) - mean * mean + 1e-5f);
        char* dst = smc + r * RSB + (h >> 1) * 4;
#pragma unroll
        for (int j = 0; j < 16; j++) {
            int k = h + j * 4;
            float4 gg = ld4(ng + k), bb = ld4(nb + k);
            float ox = fmaxf((av[j].x - mean) * kinv * gg.x + bb.x, 0.f);
            float oy = fmaxf((av[j].y - mean) * kinv * gg.y + bb.y, 0.f);
            float oz = fmaxf((av[j].z - mean) * kinv * gg.z + bb.z, 0.f);
            float ow = fmaxf((av[j].w - mean) * kinv * gg.w + bb.w, 0.f);
            uint2 v;
            v.x = h2(ox, oy);
            v.y = h2(oz, ow);
            *(uint2*)(dst + j * 8) = v;
        }
        if (zero_tmp) {
            float4 z = make_float4(0.f, 0.f, 0.f, 0.f);
#pragma unroll
            for (int j = 0; j < 16; j++) *(float4*)(xp + j * 4) = z;
        }
    }
    cp_wait<0>();
    __syncthreads();

    uint32_t aBase = sb
        + (uint32_t)(wm * 32 + (lane & 7) + ((lane & 8) ? 8 : 0)) * RSB
        + ((lane & 16) ? 16 : 0);
    uint32_t bBase = sb + 34816
        + (uint32_t)(wn * 64 + (lane & 7) + ((lane & 16) ? 8 : 0)) * RSB
        + ((lane & 8) ? 16 : 0);

    float acc[2][8][4];
#pragma unroll
    for (int tm = 0; tm < 2; tm++)
#pragma unroll
        for (int nt = 0; nt < 8; nt++)
#pragma unroll
            for (int j = 0; j < 4; j++) acc[tm][nt][j] = 0.f;

#pragma unroll
    for (int ks = 0; ks < 8; ks++) {
        uint32_t af0[4], af1[4];
        LDSM_X4(af0[0], af0[1], af0[2], af0[3], aBase + ks * 32);
        LDSM_X4(af1[0], af1[1], af1[2], af1[3], aBase + 16 * RSB + ks * 32);
#pragma unroll
        for (int g = 0; g < 4; g++) {
            uint32_t bf[4];
            LDSM_X4(bf[0], bf[1], bf[2], bf[3], bBase + (uint32_t)g * 16 * RSB + ks * 32);
            MMA_F16(acc[0][2 * g],     af0[0], af0[1], af0[2], af0[3], bf[0], bf[1]);
            MMA_F16(acc[1][2 * g],     af1[0], af1[1], af1[2], af1[3], bf[0], bf[1]);
            MMA_F16(acc[0][2 * g + 1], af0[0], af0[1], af0[2], af0[3], bf[2], bf[3]);
            MMA_F16(acc[1][2 * g + 1], af1[0], af1[1], af1[2], af1[3], bf[2], bf[3]);
        }
    }
    __syncthreads();

#pragma unroll
    for (int tm = 0; tm < 2; tm++) {
        int r0 = wm * 32 + tm * 16 + gid;
#pragma unroll
        for (int nt = 0; nt < 8; nt++) {
            int cc = wn * 64 + nt * 8 + tig * 2;
            *(float2*)(Cs + r0 * CSTR + cc)       = make_float2(acc[tm][nt][0], acc[tm][nt][1]);
            *(float2*)(Cs + (r0 + 8) * CSTR + cc) = make_float2(acc[tm][nt][2], acc[tm][nt][3]);
        }
    }
    __syncthreads();

    for (int r = warp; r < 128; r += 8) {
        int c = lane * 4;
        float4 x = *(float4*)(Cs + r * CSTR + c);
        float m, k;
        gn_stats(x, m, k);
        float4 gg = ld4(g2 + c), bb = ld4(b2 + c);
        long grow = rowBase + r;
        float4 old = ld4(feat + grow * 128 + c);
        float4 o;
        o.x = fmaxf((x.x - m) * k * gg.x + bb.x + old.x, 0.f);
        o.y = fmaxf((x.y - m) * k * gg.y + bb.y + old.y, 0.f);
        o.z = fmaxf((x.z - m) * k * gg.z + bb.z + old.z, 0.f);
        o.w = fmaxf((x.w - m) * k * gg.w + bb.w + old.w, 0.f);
        *(float4*)(feat + grow * 128 + c) = o;
        if (dout && grow < NN) *(float4*)(dout + grow * 128 + c) = o;
    }
}

// ---------------- host launcher ----------------
extern "C" void kernel_launch(void* const* d_in, const int* in_sizes, int n_in,
                              void* d_out, int out_size)
{
    const float* ctrs   = (const float*)d_in[0];
    const float* feats  = (const float*)d_in[1];
    const float* w_in1  = (const float*)d_in[2];
    const float* b_in1  = (const float*)d_in[3];
    const float* w_in2  = (const float*)d_in[4];
    const float* g_in   = (const float*)d_in[5];
    const float* be_in  = (const float*)d_in[6];
    const float* w_seg1 = (const float*)d_in[7];
    const float* b_seg1 = (const float*)d_in[8];
    const float* w_seg2 = (const float*)d_in[9];
    const float* g_seg  = (const float*)d_in[10];
    const float* be_seg = (const float*)d_in[11];
    const float* ctr_w  = (const float*)d_in[12];
    const float* pre_w  = (const float*)d_in[13];
    const float* suc_w  = (const float*)d_in[14];
    const float* left_w = (const float*)d_in[15];
    const float* right_w= (const float*)d_in[16];
    const float* norm_g = (const float*)d_in[17];
    const float* norm_b = (const float*)d_in[18];
    const float* ctr2_w = (const float*)d_in[19];
    const float* ctr2_g = (const float*)d_in[20];
    const float* ctr2_b = (const float*)d_in[21];
    const int* pre_u  = (const int*)d_in[22];
    const int* pre_v  = (const int*)d_in[23];
    const int* suc_u  = (const int*)d_in[24];
    const int* suc_v  = (const int*)d_in[25];
    const int* left_u = (const int*)d_in[26];
    const int* left_v = (const int*)d_in[27];
    const int* right_u= (const int*)d_in[28];
    const int* right_v= (const int*)d_in[29];

    float *feat, *tmp, *y;
    uint32_t *wimg;
    cudaGetSymbolAddress((void**)&feat, g_feat);
    cudaGetSymbolAddress((void**)&tmp,  g_tmp);
    cudaGetSymbolAddress((void**)&y,    g_y);
    cudaGetSymbolAddress((void**)&wimg, g_wimg);

    const int EB = (TOTAL_E + 255) / 256;

    static bool attr_set = false;
    if (!attr_set) {
        cudaFuncSetAttribute(enc_gemm2_kernel, cudaFuncAttributeMaxDynamicSharedMemorySize, SMEM_ENC);
        cudaFuncSetAttribute(post_kernel,      cudaFuncAttributeMaxDynamicSharedMemorySize, SMEM_POST);
        cudaFuncSetAttribute(fuse_kernel,      cudaFuncAttributeMaxDynamicSharedMemorySize, SMEM_FUSE4);
        attr_set = true;
    }

    // g_cnt zero at module load; re-zeroed by post(i=3) each call.
    place_kernel<<<EB, 256>>>(pre_u, pre_v, suc_u, suc_v, left_u, left_v, right_u, right_v);
    prep_kernel<<<64, 256>>>(pre_w, suc_w, left_w, right_w, ctr_w, ctr2_w);

    enc1_kernel<<<(NN * 32) / 256, 256>>>(ctrs, feats, w_in1, b_in1, w_seg1, b_seg1, tmp, y);
    enc_gemm2_kernel<<<dim3(NBLK, 2), 256, SMEM_ENC>>>(tmp, w_in2, y, w_seg2);
    enc2_kernel<<<NN / 8, 256>>>(tmp, g_in, be_in, y, g_seg, be_seg, feat);

    for (int i = 0; i < LL; i++) {
        fuse_kernel<<<NBLK, 512, SMEM_FUSE4>>>(feat, tmp, wimg + (size_t)i * NIMG * IMGW);
        post_kernel<<<NBLK, 256, SMEM_POST>>>(
            tmp, feat, wimg + ((size_t)i * NIMG + 15) * IMGW,
            norm_g + i * 128, norm_b + i * 128,
            ctr2_g + i * 128, ctr2_b + i * 128,
            (i == LL - 1) ? (float*)d_out : nullptr,
            (i < LL - 1) ? 1 : 0,
            (i == LL - 1) ? 1 : 0);
    }
}

// round 17
// speedup vs baseline: 1.6626x; 1.0657x over previous
#include <cuda_runtime.h>
#include <cuda_fp16.h>
#include <cstdint>

#define NN 200000
#define NPAD 200064     // 1563 * 128
#define DD 128
#define EE 200000
#define EE2 20000
#define SS 6
#define LL 4
#define NBLK 1563
#define RSW 68          // fp16 row stride in words (136 halves)
#define RSB 272         // row stride bytes
#define CSTR 132        // fp32 C stride
#define NTYPE 14
#define NBUCK (NTYPE * NBLK)
#define TOTAL_E (12 * EE + 2 * EE2)
#define CAP1 256
#define CAP2 64
#define EDGESZ (12 * NBLK * CAP1 + 2 * NBLK * CAP2)

#define IMGW (128 * RSW)        // uint32 words per prepped B image (8704)
#define IMGB (IMGW * 4)         // 34816 bytes
#define CHW  (128 * RSW)        // fp16 C buffer words
#define NIMG 16                 // per layer: 14 edge types + ctr + ctr2

// fuse smem layout (bytes)
#define F_A   0                          // A tile (ldmatrix layout): 34816
#define F_B   34816                      // B x2: 69632
#define F_C   (34816 + 69632)            // CH x2 (fp16): 69632
#define F_E   (34816 + 69632 + 69632)    // EIX: 12800
#define F_CNT (F_E + 12800)              // SCNT: 64
#define SMEM_FUSE4 (F_CNT + 64)          // 186944
#define SMEM_POST 69632
// merged encoder smem: A 34816 | B x2 69632 | Cs 67584
#define E_A 0
#define E_B 34816
#define E_C 104448
#define SMEM_ENCK 172032

// ---------------- device scratch ----------------
__device__ float g_feat[NPAD * DD];
__device__ float g_tmp [NPAD * DD];
__device__ int   g_cnt [NBUCK];
__device__ int   g_edges[EDGESZ];
__device__ uint32_t g_wimg[66 * IMGW];   // 64 layer images + w_in2 + w_seg2

__device__ __forceinline__ float4 ld4(const float* p) { return *(const float4*)(p); }

__device__ __forceinline__ uint32_t h2(float lo, float hi) {
    uint32_t r;
    asm("cvt.rn.f16x2.f32 %0, %1, %2;" : "=r"(r) : "f"(hi), "f"(lo));
    return r;
}

__device__ __forceinline__ float wsum(float s) {
#pragma unroll
    for (int o = 16; o; o >>= 1) s += __shfl_xor_sync(0xffffffffu, s, o);
    return s;
}

__device__ __forceinline__ void redv4(float* p, float4 y) {
    asm volatile("red.global.add.v4.f32 [%0], {%1,%2,%3,%4};"
                 :: "l"(p), "f"(y.x), "f"(y.y), "f"(y.z), "f"(y.w) : "memory");
}

__device__ __forceinline__ uint32_t smem_u32(const void* p) {
    uint32_t a;
    asm("{ .reg .u64 t; cvta.to.shared.u64 t, %1; cvt.u32.u64 %0, t; }" : "=r"(a) : "l"(p));
    return a;
}

__device__ __forceinline__ void cpa16(uint32_t dst, const void* src) {
    asm volatile("cp.async.cg.shared.global [%0], [%1], 16;" :: "r"(dst), "l"(src));
}
__device__ __forceinline__ void cp_commit() {
    asm volatile("cp.async.commit_group;" ::: "memory");
}
template<int N>
__device__ __forceinline__ void cp_wait() {
    asm volatile("cp.async.wait_group %0;" :: "n"(N) : "memory");
}

#define LDSM_X4(r0, r1, r2, r3, addr) \
    asm volatile("ldmatrix.sync.aligned.m8n8.x4.shared.b16 {%0,%1,%2,%3}, [%4];" \
                 : "=r"(r0), "=r"(r1), "=r"(r2), "=r"(r3) : "r"(addr))

#define MMA_F16(acc, a0, a1, a2, a3, b0, b1) \
    asm volatile( \
        "mma.sync.aligned.m16n8k16.row.col.f32.f16.f16.f32 " \
        "{%0,%1,%2,%3}, {%4,%5,%6,%7}, {%8,%9}, {%0,%1,%2,%3};\n" \
        : "+f"((acc)[0]), "+f"((acc)[1]), "+f"((acc)[2]), "+f"((acc)[3]) \
        : "r"(a0), "r"(a1), "r"(a2), "r"(a3), "r"(b0), "r"(b1))

// 16-warp (4x4 grid) warp-tile GEMM: acc += A@B^T, warp tile 32x32 (validated r13/14)
__device__ __forceinline__ void gemm_acc16(uint32_t aB, uint32_t bB, float acc[2][4][4]) {
#pragma unroll
    for (int ks = 0; ks < 8; ks++) {
        uint32_t af0[4], af1[4], bf0[4], bf1[4];
        LDSM_X4(af0[0], af0[1], af0[2], af0[3], aB + ks * 32);
        LDSM_X4(af1[0], af1[1], af1[2], af1[3], aB + 16 * RSB + ks * 32);
        LDSM_X4(bf0[0], bf0[1], bf0[2], bf0[3], bB + ks * 32);
        LDSM_X4(bf1[0], bf1[1], bf1[2], bf1[3], bB + 16 * RSB + ks * 32);
        MMA_F16(acc[0][0], af0[0], af0[1], af0[2], af0[3], bf0[0], bf0[1]);
        MMA_F16(acc[1][0], af1[0], af1[1], af1[2], af1[3], bf0[0], bf0[1]);
        MMA_F16(acc[0][1], af0[0], af0[1], af0[2], af0[3], bf0[2], bf0[3]);
        MMA_F16(acc[1][1], af1[0], af1[1], af1[2], af1[3], bf0[2], bf0[3]);
        MMA_F16(acc[0][2], af0[0], af0[1], af0[2], af0[3], bf1[0], bf1[1]);
        MMA_F16(acc[1][2], af1[0], af1[1], af1[2], af1[3], bf1[0], bf1[1]);
        MMA_F16(acc[0][3], af0[0], af0[1], af0[2], af0[3], bf1[2], bf1[3]);
        MMA_F16(acc[1][3], af1[0], af1[1], af1[2], af1[3], bf1[2], bf1[3]);
    }
}

// ---------------- GN helper ----------------
__device__ __forceinline__ void gn_stats(float4 x, float& mean, float& kinv) {
    float s  = x.x + x.y + x.z + x.w;
    float sq = x.x * x.x + x.y * x.y + x.z * x.z + x.w * x.w;
    s  = wsum(s)  * (1.f / 128.f);
    sq = wsum(sq) * (1.f / 128.f);
    mean = s;
    float var = sq - s * s;
    kinv = rsqrtf(var + 1e-5f);
}

// ---------------- weight prep: fp32 W[k][n] -> fp16 image W^T [n][k], stride RSW ----------------
__global__ __launch_bounds__(256) void prep_kernel(
    const float* __restrict__ pre_w, const float* __restrict__ suc_w,
    const float* __restrict__ left_w, const float* __restrict__ right_w,
    const float* __restrict__ ctr_w, const float* __restrict__ ctr2_w,
    const float* __restrict__ w_in2, const float* __restrict__ w_seg2)
{
    int m = blockIdx.x;              // 0..65
    const float* W;
    if (m < 64) {
        int i = m >> 4, t = m & 15;
        if (t < 6)        W = pre_w  + (size_t)(i * 6 + t) * 16384;
        else if (t < 12)  W = suc_w  + (size_t)(i * 6 + (t - 6)) * 16384;
        else if (t == 12) W = left_w  + (size_t)i * 16384;
        else if (t == 13) W = right_w + (size_t)i * 16384;
        else if (t == 14) W = ctr_w   + (size_t)i * 16384;
        else              W = ctr2_w  + (size_t)i * 16384;
    } else {
        W = (m == 64) ? w_in2 : w_seg2;
    }
    uint32_t* img = g_wimg + (size_t)m * IMGW;

    for (int e = threadIdx.x; e < 128 * 64; e += 256) {
        int n = e >> 6, kp = e & 63;
        img[n * RSW + kp] = h2(__ldg(&W[(2 * kp) * 128 + n]), __ldg(&W[(2 * kp + 1) * 128 + n]));
    }
}

// ---------------- edge buckets (type, v-block); relies on g_cnt zeroed ----------------
__global__ void place_kernel(const int* __restrict__ pre_u, const int* __restrict__ pre_v,
                             const int* __restrict__ suc_u, const int* __restrict__ suc_v,
                             const int* __restrict__ left_u, const int* __restrict__ left_v,
                             const int* __restrict__ right_u, const int* __restrict__ right_v)
{
    int idx = blockIdx.x * 256 + threadIdx.x;
    int t, u, v;
    if (idx < 6 * EE)            { t = idx / EE; u = pre_u[idx]; v = pre_v[idx]; }
    else if (idx < 12 * EE)      { int j = idx - 6 * EE; t = idx / EE; u = suc_u[j]; v = suc_v[j]; }
    else if (idx < 12 * EE + EE2){ int j = idx - 12 * EE; t = 12; u = left_u[j]; v = left_v[j]; }
    else if (idx < TOTAL_E)      { int j = idx - 12 * EE - EE2; t = 13; u = right_u[j]; v = right_v[j]; }
    else return;
    int vb = v >> 7;
    int b = t * NBLK + vb;
    int cap  = (t < 12) ? CAP1 : CAP2;
    int base = (t < 12) ? b * CAP1 : (12 * NBLK * CAP1 + ((t - 12) * NBLK + vb) * CAP2);
    int pos = atomicAdd(&g_cnt[b], 1);
    if (pos < cap) g_edges[base + pos] = u | ((v & 127) << 18);
}

// ---------------- merged encoder: h-MLPs + 2 GEMMs + GN-add-relu, one kernel ----------------
__global__ __launch_bounds__(512) void enc_kernel(
    const float* __restrict__ ctrs, const float* __restrict__ feats,
    const float* __restrict__ w_in1, const float* __restrict__ b_in1,
    const float* __restrict__ w_seg1, const float* __restrict__ b_seg1,
    const float* __restrict__ g_in, const float* __restrict__ be_in,
    const float* __restrict__ g_seg, const float* __restrict__ be_seg,
    float* __restrict__ feat, float* __restrict__ tmp,
    const uint32_t* __restrict__ BimgIn, const uint32_t* __restrict__ BimgSeg)
{
    extern __shared__ char smc[];
    float* Cs = (float*)(smc + E_C);
    uint32_t sb = smem_u32(smc);

    int tid = threadIdx.x, lane = tid & 31, warp = tid >> 5;
    int gid = lane >> 2, tig = lane & 3;
    int wm = warp >> 2, wn = warp & 3;
    long rowBase = (long)blockIdx.x * 128;
    int wrow = warp * 8;

    // async: both B images
    for (int ch = tid; ch < IMGB / 16; ch += 512)
        cpa16(sb + E_B + ch * 16, (const char*)BimgIn + ch * 16);
    for (int ch = tid; ch < IMGB / 16; ch += 512)
        cpa16(sb + E_B + IMGB + ch * 16, (const char*)BimgSeg + ch * 16);
    cp_commit();

    uint32_t aLane = (uint32_t)(wm * 32 + (lane & 7) + ((lane & 8) ? 8 : 0)) * RSB
                   + ((lane & 16) ? 16 : 0);
    uint32_t bLane = (uint32_t)(wn * 32 + (lane & 7) + ((lane & 16) ? 8 : 0)) * RSB
                   + ((lane & 8) ? 16 : 0);

    // build h_in tile (fp16 row-major)
    {
        int r = tid >> 2, q = tid & 3;
        long gr = rowBase + r;
        float c0 = 0.f, c1 = 0.f;
        if (gr < NN) { c0 = __ldg(&ctrs[2 * gr]); c1 = __ldg(&ctrs[2 * gr + 1]); }
        char* dst = smc + E_A + r * RSB + q * 64;
#pragma unroll
        for (int j = 0; j < 8; j++) {
            int c = q * 32 + j * 4;
            float4 w0 = ld4(w_in1 + c), w1 = ld4(w_in1 + 128 + c), bi = ld4(b_in1 + c);
            float hx = fmaxf(c0 * w0.x + c1 * w1.x + bi.x, 0.f);
            float hy = fmaxf(c0 * w0.y + c1 * w1.y + bi.y, 0.f);
            float hz = fmaxf(c0 * w0.z + c1 * w1.z + bi.z, 0.f);
            float hw = fmaxf(c0 * w0.w + c1 * w1.w + bi.w, 0.f);
            uint2 v;
            v.x = h2(hx, hy);
            v.y = h2(hz, hw);
            *(uint2*)(dst + j * 8) = v;
        }
    }
    cp_wait<0>();
    __syncthreads();

    // GEMM1: h_in @ w_in2
    float acc[2][4][4];
#pragma unroll
    for (int tm = 0; tm < 2; tm++)
#pragma unroll
        for (int nt = 0; nt < 4; nt++)
#pragma unroll
            for (int j = 0; j < 4; j++) acc[tm][nt][j] = 0.f;
    gemm_acc16(sb + E_A + aLane, sb + E_B + bLane, acc);

#pragma unroll
    for (int tm = 0; tm < 2; tm++) {
        int r0 = wm * 32 + tm * 16 + gid;
#pragma unroll
        for (int nt = 0; nt < 4; nt++) {
            int cc = wn * 32 + nt * 8 + tig * 2;
            *(float2*)(Cs + r0 * CSTR + cc)       = make_float2(acc[tm][nt][0], acc[tm][nt][1]);
            *(float2*)(Cs + (r0 + 8) * CSTR + cc) = make_float2(acc[tm][nt][2], acc[tm][nt][3]);
        }
    }
    __syncthreads();

    // GN1 into registers
    float g1[8][4];
#pragma unroll
    for (int j = 0; j < 8; j++) {
        int r = wrow + j, c = lane * 4;
        float4 x = *(float4*)(Cs + r * CSTR + c);
        float m, k;
        gn_stats(x, m, k);
        float4 gg = ld4(g_in + c), bb = ld4(be_in + c);
        g1[j][0] = (x.x - m) * k * gg.x + bb.x;
        g1[j][1] = (x.y - m) * k * gg.y + bb.y;
        g1[j][2] = (x.z - m) * k * gg.z + bb.z;
        g1[j][3] = (x.w - m) * k * gg.w + bb.w;
    }
    __syncthreads();

    // build h_seg tile
    {
        int r = tid >> 2, q = tid & 3;
        long gr = rowBase + r;
        float f0 = 0.f, f1 = 0.f;
        if (gr < NN) { f0 = __ldg(&feats[2 * gr]); f1 = __ldg(&feats[2 * gr + 1]); }
        char* dst = smc + E_A + r * RSB + q * 64;
#pragma unroll
        for (int j = 0; j < 8; j++) {
            int c = q * 32 + j * 4;
            float4 w0 = ld4(w_seg1 + c), w1 = ld4(w_seg1 + 128 + c), bi = ld4(b_seg1 + c);
            float hx = fmaxf(f0 * w0.x + f1 * w1.x + bi.x, 0.f);
            float hy = fmaxf(f0 * w0.y + f1 * w1.y + bi.y, 0.f);
            float hz = fmaxf(f0 * w0.z + f1 * w1.z + bi.z, 0.f);
            float hw = fmaxf(f0 * w0.w + f1 * w1.w + bi.w, 0.f);
            uint2 v;
            v.x = h2(hx, hy);
            v.y = h2(hz, hw);
            *(uint2*)(dst + j * 8) = v;
        }
    }
    __syncthreads();

    // GEMM2: h_seg @ w_seg2
#pragma unroll
    for (int tm = 0; tm < 2; tm++)
#pragma unroll
        for (int nt = 0; nt < 4; nt++)
#pragma unroll
            for (int j = 0; j < 4; j++) acc[tm][nt][j] = 0.f;
    gemm_acc16(sb + E_A + aLane, sb + E_B + IMGB + bLane, acc);

#pragma unroll
    for (int tm = 0; tm < 2; tm++) {
        int r0 = wm * 32 + tm * 16 + gid;
#pragma unroll
        for (int nt = 0; nt < 4; nt++) {
            int cc = wn * 32 + nt * 8 + tig * 2;
            *(float2*)(Cs + r0 * CSTR + cc)       = make_float2(acc[tm][nt][0], acc[tm][nt][1]);
            *(float2*)(Cs + (r0 + 8) * CSTR + cc) = make_float2(acc[tm][nt][2], acc[tm][nt][3]);
        }
    }
    __syncthreads();

    // epilogue: feat = relu(g1 + gn2); zero tmp
#pragma unroll
    for (int j = 0; j < 8; j++) {
        int r = wrow + j, c = lane * 4;
        float4 x = *(float4*)(Cs + r * CSTR + c);
        float m, k;
        gn_stats(x, m, k);
        float4 gg = ld4(g_seg + c), bb = ld4(be_seg + c);
        long grow = rowBase + r;
        float4 o;
        o.x = fmaxf(g1[j][0] + (x.x - m) * k * gg.x + bb.x, 0.f);
        o.y = fmaxf(g1[j][1] + (x.y - m) * k * gg.y + bb.y, 0.f);
        o.z = fmaxf(g1[j][2] + (x.z - m) * k * gg.z + bb.z, 0.f);
        o.w = fmaxf(g1[j][3] + (x.w - m) * k * gg.w + bb.w, 0.f);
        *(float4*)(feat + grow * 128 + c) = o;
        *(float4*)(tmp  + grow * 128 + c) = make_float4(0.f, 0.f, 0.f, 0.f);
    }
}

// ---------------- fuse: warp-specialized (w0-7 GEMM, w8-15 scatter) ----------------
__global__ __launch_bounds__(512) void fuse_kernel(
    const float* __restrict__ featIn, float* __restrict__ temp,
    const uint32_t* __restrict__ Wimg)
{
    extern __shared__ char smc[];
    uint32_t* CH  = (uint32_t*)(smc + F_C);
    int*      EIX = (int*)(smc + F_E);
    int*      SCNT= (int*)(smc + F_CNT);

    uint32_t sb = smem_u32(smc);
    uint32_t eixA = sb + F_E;

    int tid = threadIdx.x, lane = tid & 31, warp = tid >> 5;
    int gid = lane >> 2, tig = lane & 3;
    int bid = blockIdx.x;
    long rowBase = (long)bid * 128;

    int wm = (warp & 7) >> 1, wn = warp & 1;   // compute warps: 4x2 grid, tile 32x64

    // async group 0: edge indices + B(0) (all threads)
    for (int ch = tid; ch < 800; ch += 512) {
        int w = ch * 4;
        int srcw;
        if (w < 3072) {
            int t = w >> 8, off = w & 255;
            srcw = (t * NBLK + bid) * CAP1 + off;
        } else {
            int j = w - 3072;
            int t = j >> 6, off = j & 63;
            srcw = 12 * NBLK * CAP1 + (t * NBLK + bid) * CAP2 + off;
        }
        cpa16(eixA + w * 4, g_edges + srcw);
    }
    for (int ch = tid; ch < IMGB / 16; ch += 512)
        cpa16(sb + F_B + ch * 16, (const char*)Wimg + ch * 16);
    cp_commit();

    if (tid < 14) {
        int c = g_cnt[tid * NBLK + bid];
        int cap = (tid < 12) ? CAP1 : CAP2;
        SCNT[tid] = (c > cap) ? cap : c;
    }

    // A tile
    {
        int r = tid >> 2, q = tid & 3;
        const float* ap = featIn + (rowBase + r) * 128 + q * 32;
        char* dst = smc + F_A + r * RSB + q * 64;
#pragma unroll
        for (int j = 0; j < 8; j++) {
            float4 a = ld4(ap + j * 4);
            uint2 v;
            v.x = h2(a.x, a.y);
            v.y = h2(a.z, a.w);
            *(uint2*)(dst + j * 8) = v;
        }
    }

    uint32_t aBase = sb + F_A
        + (uint32_t)(wm * 32 + (lane & 7) + ((lane & 8) ? 8 : 0)) * RSB
        + ((lane & 16) ? 16 : 0);
    uint32_t bBase = sb + F_B
        + (uint32_t)(wn * 64 + (lane & 7) + ((lane & 16) ? 8 : 0)) * RSB
        + ((lane & 8) ? 16 : 0);

    for (int t = 0; t < 15; t++) {
        cp_wait<0>();
        __syncthreads();   // B(t)+edges visible; C(t-1) staged; scatter(t-2) done with CH[t&1]

        if (warp < 8) {
            // compute warps: GEMM(t) + stage C(t)
            float acc[2][8][4];
#pragma unroll
            for (int tm = 0; tm < 2; tm++)
#pragma unroll
                for (int nt = 0; nt < 8; nt++)
#pragma unroll
                    for (int j = 0; j < 4; j++) acc[tm][nt][j] = 0.f;

#pragma unroll
            for (int ks = 0; ks < 8; ks++) {
                uint32_t af0[4], af1[4];
                LDSM_X4(af0[0], af0[1], af0[2], af0[3], aBase + ks * 32);
                LDSM_X4(af1[0], af1[1], af1[2], af1[3], aBase + 16 * RSB + ks * 32);
#pragma unroll
                for (int g = 0; g < 4; g++) {
                    uint32_t bf[4];
                    LDSM_X4(bf[0], bf[1], bf[2], bf[3], bBase + (uint32_t)(t & 1) * IMGB
                            + (uint32_t)g * 16 * RSB + ks * 32);
                    MMA_F16(acc[0][2 * g],     af0[0], af0[1], af0[2], af0[3], bf[0], bf[1]);
                    MMA_F16(acc[1][2 * g],     af1[0], af1[1], af1[2], af1[3], bf[0], bf[1]);
                    MMA_F16(acc[0][2 * g + 1], af0[0], af0[1], af0[2], af0[3], bf[2], bf[3]);
                    MMA_F16(acc[1][2 * g + 1], af1[0], af1[1], af1[2], af1[3], bf[2], bf[3]);
                }
            }

            uint32_t* Cw = CH + ((t & 1) ? CHW : 0);
#pragma unroll
            for (int tm = 0; tm < 2; tm++) {
                int r0 = wm * 32 + tm * 16 + gid;
#pragma unroll
                for (int nt = 0; nt < 8; nt++) {
                    int widx = wn * 32 + nt * 4 + tig;
                    Cw[r0 * RSW + widx]       = h2(acc[tm][nt][0], acc[tm][nt][1]);
                    Cw[(r0 + 8) * RSW + widx] = h2(acc[tm][nt][2], acc[tm][nt][3]);
                }
            }
        } else {
            // scatter warps: issue B(t+1) then drain CH[(t-1)&1]
            if (t < 14) {
                const char* src = (const char*)(Wimg + (size_t)(t + 1) * IMGW);
                uint32_t dst = sb + F_B + ((t + 1) & 1) * IMGB;
                for (int ch = tid - 256; ch < IMGB / 16; ch += 256)
                    cpa16(dst + ch * 16, src + ch * 16);
                cp_commit();
            }
            if (t > 0) {
                int s = t - 1;
                int sw = warp - 8;
                int len = SCNT[s];
                int ebase = (s < 12) ? s * CAP1 : 3072 + (s - 12) * CAP2;
                const uint32_t* Crow = CH + ((s & 1) ? CHW : 0);
                for (int e = sw; e < len; e += 8) {
                    int pk = EIX[ebase + e];
                    int u  = pk & 0x3FFFF;
                    int vl = pk >> 18;
                    uint2 w = *(const uint2*)(Crow + vl * RSW + lane * 2);
                    float2 f0 = __half22float2(*(__half2*)&w.x);
                    float2 f1 = __half22float2(*(__half2*)&w.y);
                    redv4(temp + (long)u * 128 + lane * 4, make_float4(f0.x, f0.y, f1.x, f1.y));
                }
            }
        }
    }

    // drain: ctr rows only (staged in CH[0] at t=14)
    __syncthreads();
    for (int r = warp; r < 128; r += 16) {
        uint2 w = *(const uint2*)(CH + r * RSW + lane * 2);
        float2 f0 = __half22float2(*(__half2*)&w.x);
        float2 f1 = __half22float2(*(__half2*)&w.y);
        redv4(temp + (rowBase + r) * 128 + lane * 4, make_float4(f0.x, f0.y, f1.x, f1.y));
    }
}

// ---------------- post (ldmatrix + cp.async B image) ----------------
__global__ __launch_bounds__(256, 2) void post_kernel(
    float* __restrict__ tmp, float* __restrict__ feat,
    const uint32_t* __restrict__ Bimg,
    const float* __restrict__ ng, const float* __restrict__ nb,
    const float* __restrict__ g2, const float* __restrict__ b2,
    float* __restrict__ dout, int zero_tmp, int zero_cnt)
{
    extern __shared__ char smc[];
    float* Cs = (float*)(smc);

    uint32_t sb = smem_u32(smc);
    int tid = threadIdx.x, lane = tid & 31, warp = tid >> 5;
    int gid = lane >> 2, tig = lane & 3;
    int wm = warp >> 1, wn = warp & 1;
    long rowBase = (long)blockIdx.x * 128;

    for (int ch = tid; ch < IMGB / 16; ch += 256)
        cpa16(sb + 34816 + ch * 16, (const char*)Bimg + ch * 16);
    cp_commit();

    if (zero_cnt && tid < 14) g_cnt[blockIdx.x * 14 + tid] = 0;

    {
        int r = tid >> 1;
        int h = (tid & 1) * 64;
        float* xp = tmp + (rowBase + r) * 128 + h;
        float s = 0.f, sq = 0.f;
        float4 av[16];
#pragma unroll
        for (int j = 0; j < 16; j++) {
            av[j] = ld4(xp + j * 4);
            s  += av[j].x + av[j].y + av[j].z + av[j].w;
            sq += av[j].x * av[j].x + av[j].y * av[j].y + av[j].z * av[j].z + av[j].w * av[j].w;
        }
        s  += __shfl_xor_sync(0xffffffffu, s, 1);
        sq += __shfl_xor_sync(0xffffffffu, sq, 1);
        float mean = s * (1.f / 128.f);
        float kinv = rsqrtf(sq * (1.f / 128.f) - mean * mean + 1e-5f);
        char* dst = smc + r * RSB + (h >> 1) * 4;
#pragma unroll
        for (int j = 0; j < 16; j++) {
            int k = h + j * 4;
            float4 gg = ld4(ng + k), bb = ld4(nb + k);
            float ox = fmaxf((av[j].x - mean) * kinv * gg.x + bb.x, 0.f);
            float oy = fmaxf((av[j].y - mean) * kinv * gg.y + bb.y, 0.f);
            float oz = fmaxf((av[j].z - mean) * kinv * gg.z + bb.z, 0.f);
            float ow = fmaxf((av[j].w - mean) * kinv * gg.w + bb.w, 0.f);
            uint2 v;
            v.x = h2(ox, oy);
            v.y = h2(oz, ow);
            *(uint2*)(dst + j * 8) = v;
        }
        if (zero_tmp) {
            float4 z = make_float4(0.f, 0.f, 0.f, 0.f);
#pragma unroll
            for (int j = 0; j < 16; j++) *(float4*)(xp + j * 4) = z;
        }
    }
    cp_wait<0>();
    __syncthreads();

    uint32_t aBase = sb
        + (uint32_t)(wm * 32 + (lane & 7) + ((lane & 8) ? 8 : 0)) * RSB
        + ((lane & 16) ? 16 : 0);
    uint32_t bBase = sb + 34816
        + (uint32_t)(wn * 64 + (lane & 7) + ((lane & 16) ? 8 : 0)) * RSB
        + ((lane & 8) ? 16 : 0);

    float acc[2][8][4];
#pragma unroll
    for (int tm = 0; tm < 2; tm++)
#pragma unroll
        for (int nt = 0; nt < 8; nt++)
#pragma unroll
            for (int j = 0; j < 4; j++) acc[tm][nt][j] = 0.f;

#pragma unroll
    for (int ks = 0; ks < 8; ks++) {
        uint32_t af0[4], af1[4];
        LDSM_X4(af0[0], af0[1], af0[2], af0[3], aBase + ks * 32);
        LDSM_X4(af1[0], af1[1], af1[2], af1[3], aBase + 16 * RSB + ks * 32);
#pragma unroll
        for (int g = 0; g < 4; g++) {
            uint32_t bf[4];
            LDSM_X4(bf[0], bf[1], bf[2], bf[3], bBase + (uint32_t)g * 16 * RSB + ks * 32);
            MMA_F16(acc[0][2 * g],     af0[0], af0[1], af0[2], af0[3], bf[0], bf[1]);
            MMA_F16(acc[1][2 * g],     af1[0], af1[1], af1[2], af1[3], bf[0], bf[1]);
            MMA_F16(acc[0][2 * g + 1], af0[0], af0[1], af0[2], af0[3], bf[2], bf[3]);
            MMA_F16(acc[1][2 * g + 1], af1[0], af1[1], af1[2], af1[3], bf[2], bf[3]);
        }
    }
    __syncthreads();

#pragma unroll
    for (int tm = 0; tm < 2; tm++) {
        int r0 = wm * 32 + tm * 16 + gid;
#pragma unroll
        for (int nt = 0; nt < 8; nt++) {
            int cc = wn * 64 + nt * 8 + tig * 2;
            *(float2*)(Cs + r0 * CSTR + cc)       = make_float2(acc[tm][nt][0], acc[tm][nt][1]);
            *(float2*)(Cs + (r0 + 8) * CSTR + cc) = make_float2(acc[tm][nt][2], acc[tm][nt][3]);
        }
    }
    __syncthreads();

    for (int r = warp; r < 128; r += 8) {
        int c = lane * 4;
        float4 x = *(float4*)(Cs + r * CSTR + c);
        float m, k;
        gn_stats(x, m, k);
        float4 gg = ld4(g2 + c), bb = ld4(b2 + c);
        long grow = rowBase + r;
        float4 old = ld4(feat + grow * 128 + c);
        float4 o;
        o.x = fmaxf((x.x - m) * k * gg.x + bb.x + old.x, 0.f);
        o.y = fmaxf((x.y - m) * k * gg.y + bb.y + old.y, 0.f);
        o.z = fmaxf((x.z - m) * k * gg.z + bb.z + old.z, 0.f);
        o.w = fmaxf((x.w - m) * k * gg.w + bb.w + old.w, 0.f);
        *(float4*)(feat + grow * 128 + c) = o;
        if (dout && grow < NN) *(float4*)(dout + grow * 128 + c) = o;
    }
}

// ---------------- host launcher ----------------
extern "C" void kernel_launch(void* const* d_in, const int* in_sizes, int n_in,
                              void* d_out, int out_size)
{
    const float* ctrs   = (const float*)d_in[0];
    const float* feats  = (const float*)d_in[1];
    const float* w_in1  = (const float*)d_in[2];
    const float* b_in1  = (const float*)d_in[3];
    const float* w_in2  = (const float*)d_in[4];
    const float* g_in   = (const float*)d_in[5];
    const float* be_in  = (const float*)d_in[6];
    const float* w_seg1 = (const float*)d_in[7];
    const float* b_seg1 = (const float*)d_in[8];
    const float* w_seg2 = (const float*)d_in[9];
    const float* g_seg  = (const float*)d_in[10];
    const float* be_seg = (const float*)d_in[11];
    const float* ctr_w  = (const float*)d_in[12];
    const float* pre_w  = (const float*)d_in[13];
    const float* suc_w  = (const float*)d_in[14];
    const float* left_w = (const float*)d_in[15];
    const float* right_w= (const float*)d_in[16];
    const float* norm_g = (const float*)d_in[17];
    const float* norm_b = (const float*)d_in[18];
    const float* ctr2_w = (const float*)d_in[19];
    const float* ctr2_g = (const float*)d_in[20];
    const float* ctr2_b = (const float*)d_in[21];
    const int* pre_u  = (const int*)d_in[22];
    const int* pre_v  = (const int*)d_in[23];
    const int* suc_u  = (const int*)d_in[24];
    const int* suc_v  = (const int*)d_in[25];
    const int* left_u = (const int*)d_in[26];
    const int* left_v = (const int*)d_in[27];
    const int* right_u= (const int*)d_in[28];
    const int* right_v= (const int*)d_in[29];

    float *feat, *tmp;
    uint32_t *wimg;
    cudaGetSymbolAddress((void**)&feat, g_feat);
    cudaGetSymbolAddress((void**)&tmp,  g_tmp);
    cudaGetSymbolAddress((void**)&wimg, g_wimg);

    const int EB = (TOTAL_E + 255) / 256;

    static bool attr_set = false;
    if (!attr_set) {
        cudaFuncSetAttribute(enc_kernel,  cudaFuncAttributeMaxDynamicSharedMemorySize, SMEM_ENCK);
        cudaFuncSetAttribute(post_kernel, cudaFuncAttributeMaxDynamicSharedMemorySize, SMEM_POST);
        cudaFuncSetAttribute(fuse_kernel, cudaFuncAttributeMaxDynamicSharedMemorySize, SMEM_FUSE4);
        attr_set = true;
    }

    // g_cnt zero at module load; re-zeroed by post(i=3) each call.
    place_kernel<<<EB, 256>>>(pre_u, pre_v, suc_u, suc_v, left_u, left_v, right_u, right_v);
    prep_kernel<<<66, 256>>>(pre_w, suc_w, left_w, right_w, ctr_w, ctr2_w, w_in2, w_seg2);

    enc_kernel<<<NBLK, 512, SMEM_ENCK>>>(
        ctrs, feats, w_in1, b_in1, w_seg1, b_seg1,
        g_in, be_in, g_seg, be_seg, feat, tmp,
        wimg + (size_t)64 * IMGW, wimg + (size_t)65 * IMGW);

    for (int i = 0; i < LL; i++) {
        fuse_kernel<<<NBLK, 512, SMEM_FUSE4>>>(feat, tmp, wimg + (size_t)i * NIMG * IMGW);
        post_kernel<<<NBLK, 256, SMEM_POST>>>(
            tmp, feat, wimg + ((size_t)i * NIMG + 15) * IMGW,
            norm_g + i * 128, norm_b + i * 128,
            ctr2_g + i * 128, ctr2_b + i * 128,
            (i == LL - 1) ? (float*)d_out : nullptr,
            (i < LL - 1) ? 1 : 0,
            (i == LL - 1) ? 1 : 0);
    }
}